// round 7
// baseline (speedup 1.0000x reference)
#include <cuda_runtime.h>

// ---------------------------------------------------------------------------
// SimplifiedHAttention — closed form, full fp32, with the normalizer Z
// computed in the SAME reduction order as the reference's XLA:GPU row-reduce.
//
// Structure (validated R3-R5: all errors ~1e-3, purely numeric):
//   * q/k projections dead code.
//   * lev[i,j] = 0 (j>=i), 1 (j==i-1, i odd), 2 (other j<i).
//   * out[b,h,i] = w0*Suf(i) + w1*edge(i) + w2*(Pre(i)-edge(i)),
//     w_l = fdiv_rn(c_l, Z), c0=hier[b,h,0], c1=0.5*hier[b,h,1],
//     c2=0.25*hier[b,h,2].
//
// Numerics post-mortem (R3 1.21e-3 / R4-exact 1.41e-3 / R5-tf32 1.83e-3):
// the reference's OWN fp32 rounding of Z = jnp.sum(weights,-1) dominates on
// near-singular rows (|Z| ~ 0.01-0.1, partials ~1e3). Exact Z does NOT match
// it; we must replicate XLA:GPU's reduction tree: 1024 pair-partials
// (vec2), per-warp shfl_down tree (16,8,4,2,1), cross-warp tree of the 32
// warp results, then + 1e-8. Uniform 64-element chunks collapse bit-exactly
// to 64*c (pure doublings), so only boundary warps are simulated.
// ---------------------------------------------------------------------------

#define B_ 2
#define S_ 2048
#define E_ 1024
#define H_ 16
#define TS 128
#define NT (S_ / TS)

static_assert(S_ % TS == 0, "tile");

__device__ float g_vm [(size_t)B_ * S_ * E_];   // masked V projection
__device__ float g_pre[(size_t)B_ * S_ * E_];   // within-tile excl fwd prefix
__device__ float g_suf[(size_t)B_ * S_ * E_];   // within-tile incl bwd suffix
__device__ float g_att[(size_t)B_ * S_ * E_];   // attention output
__device__ float g_tsum [(size_t)B_ * NT * E_];
__device__ float g_tofff[(size_t)B_ * NT * E_];
__device__ float g_toffb[(size_t)B_ * NT * E_];
__device__ float4 g_wts[(size_t)B_ * H_ * S_];  // {w0,w1,w2} per (b,h,i)

// ---------------------------------------------------------------------------
// GEMM: C[m,n] = rowmask(m) * ( sum_k A[m,k]*W[n,k] + bias[n] )   (A @ W^T)
// Full fp32. 128x128 tile, BK=16, 256 threads, 8x8 micro, f32x2 FFMA2.
// ---------------------------------------------------------------------------
#define BM 128
#define BN 128
#define BKT 16
#define SPAD 4

__global__ __launch_bounds__(256, 2)
void sgemm_nt_kernel(const float* __restrict__ A, const float* __restrict__ W,
                     const float* __restrict__ bias, const int* __restrict__ mask,
                     float* __restrict__ C, int K)
{
    __shared__ float As[BKT][BM + SPAD];
    __shared__ float Ws[BKT][BN + SPAD];

    const int tid = threadIdx.x;
    const int tx = tid & 15;
    const int ty = tid >> 4;
    const int row0 = blockIdx.y * BM;
    const int col0 = blockIdx.x * BN;

    unsigned long long acc2[8][4];
    #pragma unroll
    for (int i = 0; i < 8; i++)
        #pragma unroll
        for (int jp = 0; jp < 4; jp++)
            acc2[i][jp] = 0ULL;

    for (int k0 = 0; k0 < K; k0 += BKT) {
        #pragma unroll
        for (int i = 0; i < 2; i++) {
            int f  = tid + i * 256;
            int r  = f >> 2;
            int kq = (f & 3) << 2;
            float4 va = *(const float4*)(A + (size_t)(row0 + r) * K + k0 + kq);
            As[kq + 0][r] = va.x; As[kq + 1][r] = va.y;
            As[kq + 2][r] = va.z; As[kq + 3][r] = va.w;
            float4 vw = *(const float4*)(W + (size_t)(col0 + r) * K + k0 + kq);
            Ws[kq + 0][r] = vw.x; Ws[kq + 1][r] = vw.y;
            Ws[kq + 2][r] = vw.z; Ws[kq + 3][r] = vw.w;
        }
        __syncthreads();

        #pragma unroll
        for (int kk = 0; kk < BKT; kk++) {
            ulonglong2 wva = *(const ulonglong2*)&Ws[kk][tx * 8];
            ulonglong2 wvb = *(const ulonglong2*)&Ws[kk][tx * 8 + 4];
            unsigned long long w2[4] = {wva.x, wva.y, wvb.x, wvb.y};
            float4 a0 = *(const float4*)&As[kk][ty * 8];
            float4 a1 = *(const float4*)&As[kk][ty * 8 + 4];
            float a[8] = {a0.x, a0.y, a0.z, a0.w, a1.x, a1.y, a1.z, a1.w};

            #pragma unroll
            for (int i = 0; i < 8; i++) {
                unsigned long long ai;
                asm("mov.b64 %0, {%1, %1};" : "=l"(ai) : "f"(a[i]));
                #pragma unroll
                for (int jp = 0; jp < 4; jp++) {
                    asm("fma.rn.f32x2 %0, %1, %2, %0;"
                        : "+l"(acc2[i][jp]) : "l"(ai), "l"(w2[jp]));
                }
            }
        }
        __syncthreads();
    }

    #pragma unroll
    for (int i = 0; i < 8; i++) {
        int r = row0 + ty * 8 + i;
        float mrow = mask ? (float)mask[r] : 1.0f;
        float vals[8];
        #pragma unroll
        for (int jp = 0; jp < 4; jp++) {
            float lo, hi;
            asm("mov.b64 {%0, %1}, %2;" : "=f"(lo), "=f"(hi) : "l"(acc2[i][jp]));
            vals[2 * jp] = lo; vals[2 * jp + 1] = hi;
        }
        #pragma unroll
        for (int j0 = 0; j0 < 8; j0 += 4) {
            int c = col0 + tx * 8 + j0;
            float4 o;
            o.x = mrow * (vals[j0 + 0] + bias[c + 0]);
            o.y = mrow * (vals[j0 + 1] + bias[c + 1]);
            o.z = mrow * (vals[j0 + 2] + bias[c + 2]);
            o.w = mrow * (vals[j0 + 3] + bias[c + 3]);
            *(float4*)(C + (size_t)r * E_ + c) = o;
        }
    }
}

// ---------------------------------------------------------------------------
// K2: within-tile fwd-exclusive prefix + bwd-inclusive suffix along S.
// ---------------------------------------------------------------------------
__global__ __launch_bounds__(256)
void scan_local_kernel(const float* __restrict__ vm, float* __restrict__ pre,
                       float* __restrict__ suf, float* __restrict__ tsum)
{
    int e = blockIdx.x * 256 + threadIdx.x;
    int t = blockIdx.y;
    int b = blockIdx.z;
    size_t cbase = ((size_t)b * S_ + (size_t)t * TS) * E_ + e;
    const float* src = vm + cbase;
    float* pdst = pre + cbase;
    float* sdst = suf + cbase;

    float acc = 0.0f;
    #pragma unroll 8
    for (int s = 0; s < TS; s++) {
        float v = src[(size_t)s * E_];
        pdst[(size_t)s * E_] = acc;
        acc += v;
    }
    tsum[((size_t)b * NT + t) * E_ + e] = acc;

    acc = 0.0f;
    #pragma unroll 8
    for (int s = TS - 1; s >= 0; s--) {
        float v = src[(size_t)s * E_];
        acc += v;
        sdst[(size_t)s * E_] = acc;
    }
}

// ---------------------------------------------------------------------------
// K3: cross-tile fwd/bwd offsets.
// ---------------------------------------------------------------------------
__global__ __launch_bounds__(256)
void scan_tiles_kernel(const float* __restrict__ tsum,
                       float* __restrict__ toff_f, float* __restrict__ toff_b)
{
    int e = blockIdx.x * 256 + threadIdx.x;
    int b = blockIdx.y;
    float ts[NT];
    #pragma unroll
    for (int t = 0; t < NT; t++)
        ts[t] = tsum[((size_t)b * NT + t) * E_ + e];
    float acc = 0.0f;
    #pragma unroll
    for (int t = 0; t < NT; t++) {
        toff_f[((size_t)b * NT + t) * E_ + e] = acc;
        acc += ts[t];
    }
    acc = 0.0f;
    #pragma unroll
    for (int t = NT - 1; t >= 0; t--) {
        toff_b[((size_t)b * NT + t) * E_ + e] = acc;
        acc += ts[t];
    }
}

// ---------------------------------------------------------------------------
// K_w: per-(b,h,i) weights with Z in XLA:GPU row-reduce order.
//   leaves: p_t = w(2t) + w(2t+1), t = 0..1023  (vec-2 pair partials)
//   per-warp: shfl_down tree, offsets 16,8,4,2,1  (warp w covers j in
//             [64w, 64w+64))
//   cross-warp: 32 warp results, same shfl tree; Z = total + 1e-8f.
// Uniform chunks (all c0 or all c2) reduce bit-exactly to 64*c (doublings).
// One thread per (b,h,i); ~200 flops each.
// ---------------------------------------------------------------------------
__device__ __forceinline__ float wval(int j, int i, int odd,
                                      float c0, float c1, float c2)
{
    if (j >= i) return c0;
    if (odd && j == i - 1) return c1;
    return c2;
}

__global__ __launch_bounds__(256)
void weights_kernel(const float* __restrict__ hier, float4* __restrict__ wts)
{
    int i = blockIdx.x * 256 + threadIdx.x;
    int h = blockIdx.y;
    int b = blockIdx.z;
    const float* hp = hier + ((size_t)b * H_ + h) * 3;
    float c0 = hp[0];
    float c1 = __fmul_rn(0.5f,  hp[1]);   // exact
    float c2 = __fmul_rn(0.25f, hp[2]);   // exact
    int odd = i & 1;

    float r[32];
    #pragma unroll 1
    for (int w = 0; w < 32; w++) {
        int jlo = w << 6;
        int jhi = jlo + 63;
        if (jlo >= i) {                      // entire chunk j >= i
            r[w] = __fmul_rn(64.0f, c0);     // == doubling chain, bit-exact
        } else if (jhi < i && !(odd && (i - 1) <= jhi)) {
            r[w] = __fmul_rn(64.0f, c2);     // entire chunk plain level-2
        } else {
            float p[32];
            #pragma unroll
            for (int t = 0; t < 32; t++) {
                int j = jlo + 2 * t;
                p[t] = __fadd_rn(wval(j, i, odd, c0, c1, c2),
                                 wval(j + 1, i, odd, c0, c1, c2));
            }
            #pragma unroll
            for (int s = 16; s > 0; s >>= 1)
                #pragma unroll
                for (int l = 0; l < 16; l++)
                    if (l < s) p[l] = __fadd_rn(p[l], p[l + s]);
            r[w] = p[0];
        }
    }
    #pragma unroll
    for (int s = 16; s > 0; s >>= 1)
        #pragma unroll
        for (int l = 0; l < 16; l++)
            if (l < s) r[l] = __fadd_rn(r[l], r[l + s]);

    float Z = __fadd_rn(r[0], 1e-8f);
    float4 o;
    o.x = __fdiv_rn(c0, Z);
    o.y = __fdiv_rn(c1, Z);
    o.z = __fdiv_rn(c2, Z);
    o.w = 0.0f;
    wts[((size_t)b * H_ + h) * S_ + i] = o;
}

// ---------------------------------------------------------------------------
// K4: combine. att = w0*Suf + w1*edge + w2*(Pre-edge)
// ---------------------------------------------------------------------------
__global__ __launch_bounds__(256)
void combine_kernel(const float* __restrict__ pre, const float* __restrict__ suf,
                    const float* __restrict__ toff_f, const float* __restrict__ toff_b,
                    const float* __restrict__ vm, const float4* __restrict__ wts,
                    float* __restrict__ att)
{
    int i = blockIdx.x;
    int b = blockIdx.y;
    int odd = i & 1;
    int t = i >> 7;                                   // TS = 128

    #pragma unroll
    for (int c = 0; c < E_ / 256; c++) {
        int e = threadIdx.x + c * 256;
        int h = e >> 6;                               // dh = 64
        float4 w = wts[((size_t)b * H_ + h) * S_ + i];

        size_t base = ((size_t)b * S_ + i) * E_ + e;
        size_t tidx = ((size_t)b * NT + t) * E_ + e;
        float p  = pre[base] + toff_f[tidx];
        float sf = suf[base] + toff_b[tidx];
        float edge = odd ? vm[base - E_] : 0.0f;
        att[base] = w.x * sf + w.y * edge + w.z * (p - edge);
    }
}

// ---------------------------------------------------------------------------
// Launch. Inputs (metadata order):
// 0:x 1:attention_mask 2:level_indices(unused) 3:Wq 4:bq 5:Wk 6:bk
// 7:Wv 8:bv 9:hier 10:Wo 11:bo
// ---------------------------------------------------------------------------
extern "C" void kernel_launch(void* const* d_in, const int* in_sizes, int n_in,
                              void* d_out, int out_size)
{
    const float* x    = (const float*)d_in[0];
    const int*   am   = (const int*)  d_in[1];
    const float* Wv   = (const float*)d_in[7];
    const float* bv   = (const float*)d_in[8];
    const float* hier = (const float*)d_in[9];
    const float* Wo   = (const float*)d_in[10];
    const float* bo   = (const float*)d_in[11];
    float* out = (float*)d_out;

    float *vm, *pre, *suf, *att, *tsum, *toff_f, *toff_b;
    float4* wts;
    cudaGetSymbolAddress((void**)&vm,     g_vm);
    cudaGetSymbolAddress((void**)&pre,    g_pre);
    cudaGetSymbolAddress((void**)&suf,    g_suf);
    cudaGetSymbolAddress((void**)&att,    g_att);
    cudaGetSymbolAddress((void**)&tsum,   g_tsum);
    cudaGetSymbolAddress((void**)&toff_f, g_tofff);
    cudaGetSymbolAddress((void**)&toff_b, g_toffb);
    cudaGetSymbolAddress((void**)&wts,    g_wts);

    dim3 gemm_grid(E_ / BN, (B_ * S_) / BM);   // (8, 32)

    // K1: vm = mask * (x @ Wv^T + bv)
    sgemm_nt_kernel<<<gemm_grid, 256>>>(x, Wv, bv, am, vm, E_);

    // K_w: weights with XLA-tree Z
    weights_kernel<<<dim3(S_ / 256, H_, B_), 256>>>(hier, wts);

    // K2/K3: hierarchical fwd/bwd scans along S
    scan_local_kernel<<<dim3(E_ / 256, NT, B_), 256>>>(vm, pre, suf, tsum);
    scan_tiles_kernel<<<dim3(E_ / 256, B_), 256>>>(tsum, toff_f, toff_b);

    // K4: closed-form hierarchical attention
    combine_kernel<<<dim3(S_, B_), 256>>>(pre, suf, toff_f, toff_b, vm, wts, att);

    // K5: out = att @ Wo^T + bo
    sgemm_nt_kernel<<<gemm_grid, 256>>>(att, Wo, bo, nullptr, out, E_);
}

// round 8
// speedup vs baseline: 2.0945x; 2.0945x over previous
#include <cuda_runtime.h>
#include <cuda_bf16.h>

// ---------------------------------------------------------------------------
// SimplifiedHAttention — closed form + XLA-tree Z (R7, passed 7.4e-6), with
// both GEMMs moved to tensor cores via bf16 split-3 emulation:
//   A@W ~= Ah@Wh + Ah@Wl + Al@Wh   (hi/lo bf16 split, fp32 HMMA accum)
// Error ~2e-5 rel vs 1e-3 threshold. Scans / weights kernels unchanged.
// ---------------------------------------------------------------------------

#define B_ 2
#define S_ 2048
#define E_ 1024
#define H_ 16
#define TS 128
#define NT (S_ / TS)
#define M_ (B_ * S_)        // 4096 GEMM rows
#define GK E_               // 1024 GEMM K
#define TLD 40              // smem row stride in bf16 (80B: 16B-aligned, conflict-free)

static_assert(S_ % TS == 0, "tile");

__device__ float g_vm [(size_t)B_ * S_ * E_];
__device__ float g_pre[(size_t)B_ * S_ * E_];
__device__ float g_suf[(size_t)B_ * S_ * E_];
__device__ float g_tsum [(size_t)B_ * NT * E_];
__device__ float g_tofff[(size_t)B_ * NT * E_];
__device__ float g_toffb[(size_t)B_ * NT * E_];
__device__ float4 g_wts[(size_t)B_ * H_ * S_];
// bf16 split operands
__device__ __nv_bfloat16 g_xh [(size_t)M_ * E_];
__device__ __nv_bfloat16 g_xl [(size_t)M_ * E_];
__device__ __nv_bfloat16 g_ath[(size_t)M_ * E_];
__device__ __nv_bfloat16 g_atl[(size_t)M_ * E_];
__device__ __nv_bfloat16 g_wvh[(size_t)E_ * E_];
__device__ __nv_bfloat16 g_wvl[(size_t)E_ * E_];
__device__ __nv_bfloat16 g_woh[(size_t)E_ * E_];
__device__ __nv_bfloat16 g_wol[(size_t)E_ * E_];

// ---------------------------------------------------------------------------
// hi/lo bf16 split helpers
// ---------------------------------------------------------------------------
__device__ __forceinline__ void split_bf16(float a, __nv_bfloat16& hi, __nv_bfloat16& lo)
{
    hi = __float2bfloat16_rn(a);
    lo = __float2bfloat16_rn(__fadd_rn(a, -__bfloat162float(hi)));
}

__global__ __launch_bounds__(256)
void split_kernel(const float* __restrict__ src, __nv_bfloat16* __restrict__ hi,
                  __nv_bfloat16* __restrict__ lo, int n4)
{
    int i = blockIdx.x * 256 + threadIdx.x;
    if (i >= n4) return;
    float4 v = ((const float4*)src)[i];
    __nv_bfloat16 h0,h1,h2,h3,l0,l1,l2,l3;
    split_bf16(v.x,h0,l0); split_bf16(v.y,h1,l1);
    split_bf16(v.z,h2,l2); split_bf16(v.w,h3,l3);
    ((ushort4*)hi)[i] = make_ushort4(__bfloat16_as_ushort(h0), __bfloat16_as_ushort(h1),
                                     __bfloat16_as_ushort(h2), __bfloat16_as_ushort(h3));
    ((ushort4*)lo)[i] = make_ushort4(__bfloat16_as_ushort(l0), __bfloat16_as_ushort(l1),
                                     __bfloat16_as_ushort(l2), __bfloat16_as_ushort(l3));
}

// ---------------------------------------------------------------------------
// Split-bf16 tensor-core GEMM: C[m,n] = rowmask(m)*(sum_k A[m,k]W[n,k] + bias[n])
// A,W given as bf16 hi/lo pairs. 128x128 block, 8 warps (2m x 4n), warp tile
// 64x32, mma.sync.m16n8k16 bf16->fp32. BK=32, cp.async double buffer.
// ---------------------------------------------------------------------------
__device__ __forceinline__ void cpasync16(void* dst, const void* src)
{
    unsigned d = (unsigned)__cvta_generic_to_shared(dst);
    asm volatile("cp.async.cg.shared.global [%0], [%1], 16;" :: "r"(d), "l"(src));
}

__device__ __forceinline__ void mma_bf16(float* c, const unsigned* a, const unsigned* b)
{
    asm volatile(
        "mma.sync.aligned.m16n8k16.row.col.f32.bf16.bf16.f32 "
        "{%0,%1,%2,%3}, {%4,%5,%6,%7}, {%8,%9}, {%0,%1,%2,%3};\n"
        : "+f"(c[0]), "+f"(c[1]), "+f"(c[2]), "+f"(c[3])
        : "r"(a[0]), "r"(a[1]), "r"(a[2]), "r"(a[3]), "r"(b[0]), "r"(b[1]));
}

#define STAGE_BF16 (4 * 128 * TLD)     // Ah,Al,Wh,Wl tiles per stage (bf16 count)
#define GSMEM_BYTES (2 * STAGE_BF16 * 2)

__global__ __launch_bounds__(256)
void gemm_split_kernel(const __nv_bfloat16* __restrict__ Ah,
                       const __nv_bfloat16* __restrict__ Al,
                       const __nv_bfloat16* __restrict__ Wh,
                       const __nv_bfloat16* __restrict__ Wl,
                       const float* __restrict__ bias,
                       const int* __restrict__ mask,
                       float* __restrict__ C)
{
    extern __shared__ __nv_bfloat16 sm[];
    const int tid  = threadIdx.x;
    const int lane = tid & 31;
    const int w    = tid >> 5;
    const int wm   = w >> 2;           // 0..1
    const int wn   = w & 3;            // 0..3
    const int row0 = blockIdx.y * 128;
    const int col0 = blockIdx.x * 128;
    const int lr   = lane >> 2;        // 0..7
    const int lq   = (lane & 3) << 1;  // 0,2,4,6

    float acc[4][4][4];
    #pragma unroll
    for (int ms = 0; ms < 4; ms++)
        #pragma unroll
        for (int ns = 0; ns < 4; ns++)
            #pragma unroll
            for (int t = 0; t < 4; t++) acc[ms][ns][t] = 0.0f;

    // copy one 128x32 bf16 tile x4 arrays into a stage
    #define COPY_STAGE(stg, kbase) do {                                            \
        __nv_bfloat16* sb = sm + (stg) * STAGE_BF16;                               \
        _Pragma("unroll")                                                          \
        for (int half = 0; half < 2; half++) {                                     \
            int f  = tid + half * 256;                                             \
            int r  = f >> 2;                                                       \
            int cq = (f & 3) << 3;                                                 \
            size_t ga = (size_t)(row0 + r) * GK + (kbase) + cq;                    \
            size_t gw = (size_t)(col0 + r) * GK + (kbase) + cq;                    \
            cpasync16(sb + 0 * 128 * TLD + r * TLD + cq, Ah + ga);                 \
            cpasync16(sb + 1 * 128 * TLD + r * TLD + cq, Al + ga);                 \
            cpasync16(sb + 2 * 128 * TLD + r * TLD + cq, Wh + gw);                 \
            cpasync16(sb + 3 * 128 * TLD + r * TLD + cq, Wl + gw);                 \
        }                                                                          \
    } while (0)

    COPY_STAGE(0, 0);
    asm volatile("cp.async.commit_group;");

    const int NITER = GK / 32;     // 32
    for (int it = 0; it < NITER; it++) {
        if (it + 1 < NITER) COPY_STAGE((it + 1) & 1, (it + 1) * 32);
        asm volatile("cp.async.commit_group;");
        asm volatile("cp.async.wait_group 1;");
        __syncthreads();

        const __nv_bfloat16* sb  = sm + (it & 1) * STAGE_BF16;
        const __nv_bfloat16* sAh = sb;
        const __nv_bfloat16* sAl = sb + 1 * 128 * TLD;
        const __nv_bfloat16* sWh = sb + 2 * 128 * TLD;
        const __nv_bfloat16* sWl = sb + 3 * 128 * TLD;

        #pragma unroll
        for (int kk = 0; kk < 32; kk += 16) {
            unsigned bh[4][2], bl[4][2];
            #pragma unroll
            for (int ns = 0; ns < 4; ns++) {
                int nr = (wn * 32 + ns * 8 + lr) * TLD + kk + lq;
                bh[ns][0] = *(const unsigned*)(sWh + nr);
                bh[ns][1] = *(const unsigned*)(sWh + nr + 8);
                bl[ns][0] = *(const unsigned*)(sWl + nr);
                bl[ns][1] = *(const unsigned*)(sWl + nr + 8);
            }
            #pragma unroll
            for (int ms = 0; ms < 4; ms++) {
                int mr = (wm * 64 + ms * 16 + lr) * TLD + kk + lq;
                unsigned ah[4], al[4];
                ah[0] = *(const unsigned*)(sAh + mr);
                ah[1] = *(const unsigned*)(sAh + mr + 8 * TLD);
                ah[2] = *(const unsigned*)(sAh + mr + 8);
                ah[3] = *(const unsigned*)(sAh + mr + 8 * TLD + 8);
                al[0] = *(const unsigned*)(sAl + mr);
                al[1] = *(const unsigned*)(sAl + mr + 8 * TLD);
                al[2] = *(const unsigned*)(sAl + mr + 8);
                al[3] = *(const unsigned*)(sAl + mr + 8 * TLD + 8);
                #pragma unroll
                for (int ns = 0; ns < 4; ns++) {
                    mma_bf16(acc[ms][ns], ah, bh[ns]);
                    mma_bf16(acc[ms][ns], ah, bl[ns]);
                    mma_bf16(acc[ms][ns], al, bh[ns]);
                }
            }
        }
        __syncthreads();
    }

    // Epilogue: bias + optional row mask.
    #pragma unroll
    for (int ms = 0; ms < 4; ms++) {
        int r = row0 + wm * 64 + ms * 16 + lr;
        float m0 = mask ? (float)mask[r]     : 1.0f;
        float m1 = mask ? (float)mask[r + 8] : 1.0f;
        #pragma unroll
        for (int ns = 0; ns < 4; ns++) {
            int c = col0 + wn * 32 + ns * 8 + lq;
            float b0 = bias[c], b1 = bias[c + 1];
            float2 o0 = make_float2(m0 * (acc[ms][ns][0] + b0),
                                    m0 * (acc[ms][ns][1] + b1));
            float2 o1 = make_float2(m1 * (acc[ms][ns][2] + b0),
                                    m1 * (acc[ms][ns][3] + b1));
            *(float2*)(C + (size_t)r * E_ + c)       = o0;
            *(float2*)(C + (size_t)(r + 8) * E_ + c) = o1;
        }
    }
}

// ---------------------------------------------------------------------------
// K2: within-tile fwd-exclusive prefix + bwd-inclusive suffix along S.
// ---------------------------------------------------------------------------
__global__ __launch_bounds__(256)
void scan_local_kernel(const float* __restrict__ vm, float* __restrict__ pre,
                       float* __restrict__ suf, float* __restrict__ tsum)
{
    int e = blockIdx.x * 256 + threadIdx.x;
    int t = blockIdx.y;
    int b = blockIdx.z;
    size_t cbase = ((size_t)b * S_ + (size_t)t * TS) * E_ + e;
    const float* src = vm + cbase;
    float* pdst = pre + cbase;
    float* sdst = suf + cbase;

    float acc = 0.0f;
    #pragma unroll 8
    for (int s = 0; s < TS; s++) {
        float v = src[(size_t)s * E_];
        pdst[(size_t)s * E_] = acc;
        acc += v;
    }
    tsum[((size_t)b * NT + t) * E_ + e] = acc;

    acc = 0.0f;
    #pragma unroll 8
    for (int s = TS - 1; s >= 0; s--) {
        float v = src[(size_t)s * E_];
        acc += v;
        sdst[(size_t)s * E_] = acc;
    }
}

// ---------------------------------------------------------------------------
// K3: cross-tile fwd/bwd offsets.
// ---------------------------------------------------------------------------
__global__ __launch_bounds__(256)
void scan_tiles_kernel(const float* __restrict__ tsum,
                       float* __restrict__ toff_f, float* __restrict__ toff_b)
{
    int e = blockIdx.x * 256 + threadIdx.x;
    int b = blockIdx.y;
    float ts[NT];
    #pragma unroll
    for (int t = 0; t < NT; t++)
        ts[t] = tsum[((size_t)b * NT + t) * E_ + e];
    float acc = 0.0f;
    #pragma unroll
    for (int t = 0; t < NT; t++) {
        toff_f[((size_t)b * NT + t) * E_ + e] = acc;
        acc += ts[t];
    }
    acc = 0.0f;
    #pragma unroll
    for (int t = NT - 1; t >= 0; t--) {
        toff_b[((size_t)b * NT + t) * E_ + e] = acc;
        acc += ts[t];
    }
}

// ---------------------------------------------------------------------------
// K_w: per-(b,h,i) weights, Z in XLA:GPU row-reduce order (UNCHANGED — R7
// passed with this bit pattern; do not touch).
// ---------------------------------------------------------------------------
__device__ __forceinline__ float wval(int j, int i, int odd,
                                      float c0, float c1, float c2)
{
    if (j >= i) return c0;
    if (odd && j == i - 1) return c1;
    return c2;
}

__global__ __launch_bounds__(256)
void weights_kernel(const float* __restrict__ hier, float4* __restrict__ wts)
{
    int i = blockIdx.x * 256 + threadIdx.x;
    int h = blockIdx.y;
    int b = blockIdx.z;
    const float* hp = hier + ((size_t)b * H_ + h) * 3;
    float c0 = hp[0];
    float c1 = __fmul_rn(0.5f,  hp[1]);
    float c2 = __fmul_rn(0.25f, hp[2]);
    int odd = i & 1;

    float r[32];
    #pragma unroll 1
    for (int w = 0; w < 32; w++) {
        int jlo = w << 6;
        int jhi = jlo + 63;
        if (jlo >= i) {
            r[w] = __fmul_rn(64.0f, c0);
        } else if (jhi < i && !(odd && (i - 1) <= jhi)) {
            r[w] = __fmul_rn(64.0f, c2);
        } else {
            float p[32];
            #pragma unroll
            for (int t = 0; t < 32; t++) {
                int j = jlo + 2 * t;
                p[t] = __fadd_rn(wval(j, i, odd, c0, c1, c2),
                                 wval(j + 1, i, odd, c0, c1, c2));
            }
            #pragma unroll
            for (int s = 16; s > 0; s >>= 1)
                #pragma unroll
                for (int l = 0; l < 16; l++)
                    if (l < s) p[l] = __fadd_rn(p[l], p[l + s]);
            r[w] = p[0];
        }
    }
    #pragma unroll
    for (int s = 16; s > 0; s >>= 1)
        #pragma unroll
        for (int l = 0; l < 16; l++)
            if (l < s) r[l] = __fadd_rn(r[l], r[l + s]);

    float Z = __fadd_rn(r[0], 1e-8f);
    float4 o;
    o.x = __fdiv_rn(c0, Z);
    o.y = __fdiv_rn(c1, Z);
    o.z = __fdiv_rn(c2, Z);
    o.w = 0.0f;
    wts[((size_t)b * H_ + h) * S_ + i] = o;
}

// ---------------------------------------------------------------------------
// K4: combine; emits att directly as bf16 hi/lo split (K5 GEMM operand).
// ---------------------------------------------------------------------------
__global__ __launch_bounds__(256)
void combine_kernel(const float* __restrict__ pre, const float* __restrict__ suf,
                    const float* __restrict__ toff_f, const float* __restrict__ toff_b,
                    const float* __restrict__ vm, const float4* __restrict__ wts,
                    __nv_bfloat16* __restrict__ atth, __nv_bfloat16* __restrict__ attl)
{
    int i = blockIdx.x;
    int b = blockIdx.y;
    int odd = i & 1;
    int t = i >> 7;                                   // TS = 128

    #pragma unroll
    for (int c = 0; c < E_ / 256; c++) {
        int e = threadIdx.x + c * 256;
        int h = e >> 6;                               // dh = 64
        float4 w = wts[((size_t)b * H_ + h) * S_ + i];

        size_t base = ((size_t)b * S_ + i) * E_ + e;
        size_t tidx = ((size_t)b * NT + t) * E_ + e;
        float p  = pre[base] + toff_f[tidx];
        float sf = suf[base] + toff_b[tidx];
        float edge = odd ? vm[base - E_] : 0.0f;
        float val = w.x * sf + w.y * edge + w.z * (p - edge);
        __nv_bfloat16 hi, lo;
        split_bf16(val, hi, lo);
        atth[base] = hi;
        attl[base] = lo;
    }
}

// ---------------------------------------------------------------------------
// Launch. Inputs (metadata order):
// 0:x 1:attention_mask 2:level_indices(unused) 3:Wq 4:bq 5:Wk 6:bk
// 7:Wv 8:bv 9:hier 10:Wo 11:bo
// ---------------------------------------------------------------------------
extern "C" void kernel_launch(void* const* d_in, const int* in_sizes, int n_in,
                              void* d_out, int out_size)
{
    const float* x    = (const float*)d_in[0];
    const int*   am   = (const int*)  d_in[1];
    const float* Wv   = (const float*)d_in[7];
    const float* bv   = (const float*)d_in[8];
    const float* hier = (const float*)d_in[9];
    const float* Wo   = (const float*)d_in[10];
    const float* bo   = (const float*)d_in[11];
    float* out = (float*)d_out;

    float *vm, *pre, *suf, *tsum, *toff_f, *toff_b;
    float4* wts;
    __nv_bfloat16 *xh, *xl, *ath, *atl, *wvh, *wvl, *woh, *wol;
    cudaGetSymbolAddress((void**)&vm,     g_vm);
    cudaGetSymbolAddress((void**)&pre,    g_pre);
    cudaGetSymbolAddress((void**)&suf,    g_suf);
    cudaGetSymbolAddress((void**)&tsum,   g_tsum);
    cudaGetSymbolAddress((void**)&toff_f, g_tofff);
    cudaGetSymbolAddress((void**)&toff_b, g_toffb);
    cudaGetSymbolAddress((void**)&wts,    g_wts);
    cudaGetSymbolAddress((void**)&xh,     g_xh);
    cudaGetSymbolAddress((void**)&xl,     g_xl);
    cudaGetSymbolAddress((void**)&ath,    g_ath);
    cudaGetSymbolAddress((void**)&atl,    g_atl);
    cudaGetSymbolAddress((void**)&wvh,    g_wvh);
    cudaGetSymbolAddress((void**)&wvl,    g_wvl);
    cudaGetSymbolAddress((void**)&woh,    g_woh);
    cudaGetSymbolAddress((void**)&wol,    g_wol);

    static int smem_set = 0;
    if (!smem_set) {
        cudaFuncSetAttribute(gemm_split_kernel,
                             cudaFuncAttributeMaxDynamicSharedMemorySize,
                             GSMEM_BYTES);
        smem_set = 1;
    }

    // Split prep: x, Wv, Wo -> bf16 hi/lo
    split_kernel<<<(M_ * E_ / 4 + 255) / 256, 256>>>(x,  xh,  xl,  M_ * E_ / 4);
    split_kernel<<<(E_ * E_ / 4 + 255) / 256, 256>>>(Wv, wvh, wvl, E_ * E_ / 4);
    split_kernel<<<(E_ * E_ / 4 + 255) / 256, 256>>>(Wo, woh, wol, E_ * E_ / 4);

    dim3 gemm_grid(E_ / 128, M_ / 128);   // (8, 32)

    // K1: vm = mask * (x @ Wv^T + bv)   (tensor-core split GEMM)
    gemm_split_kernel<<<gemm_grid, 256, GSMEM_BYTES>>>(xh, xl, wvh, wvl, bv, am, vm);

    // K_w: weights with XLA-tree Z
    weights_kernel<<<dim3(S_ / 256, H_, B_), 256>>>(hier, wts);

    // K2/K3: hierarchical fwd/bwd scans along S
    scan_local_kernel<<<dim3(E_ / 256, NT, B_), 256>>>(vm, pre, suf, tsum);
    scan_tiles_kernel<<<dim3(E_ / 256, B_), 256>>>(tsum, toff_f, toff_b);

    // K4: closed-form hierarchical attention -> att (bf16 hi/lo)
    combine_kernel<<<dim3(S_, B_), 256>>>(pre, suf, toff_f, toff_b, vm, wts, ath, atl);

    // K5: out = att @ Wo^T + bo
    gemm_split_kernel<<<gemm_grid, 256, GSMEM_BYTES>>>(ath, atl, woh, wol, bo,
                                                       nullptr, out);
}

// round 13
// speedup vs baseline: 2.3098x; 1.1028x over previous
#include <cuda_runtime.h>
#include <cuda_bf16.h>
#include <cstdint>

// ---------------------------------------------------------------------------
// SimplifiedHAttention — closed form + XLA-tree Z (R7) + bf16 split-3 GEMMs
// on the legacy tensor pipe (R8 passed at 230us). tcgen05 is unavailable:
// the harness lowers via compute_103 (non-'a') PTX, where tcgen05/TMEM do
// not exist (R12 ptxas failure). So we optimize the mma.sync path:
//   * ldmatrix.x4 fragment loads (12 LDSM + 48 HMMA per warp/k16, was 96 ins)
//   * __launch_bounds__(256,2): 2 CTAs/SM -> 16 warps/SM, ~single wave
// ---------------------------------------------------------------------------

#define B_ 2
#define S_ 2048
#define E_ 1024
#define H_ 16
#define TS 128
#define NT (S_ / TS)
#define M_ (B_ * S_)        // 4096 GEMM rows
#define GK E_               // 1024 GEMM K
#define TLD 40              // smem row stride in bf16 (80B)

static_assert(S_ % TS == 0, "tile");

__device__ float g_vm [(size_t)B_ * S_ * E_];
__device__ float g_pre[(size_t)B_ * S_ * E_];
__device__ float g_suf[(size_t)B_ * S_ * E_];
__device__ float g_tsum [(size_t)B_ * NT * E_];
__device__ float g_tofff[(size_t)B_ * NT * E_];
__device__ float g_toffb[(size_t)B_ * NT * E_];
__device__ float4 g_wts[(size_t)B_ * H_ * S_];
__device__ __nv_bfloat16 g_xh [(size_t)M_ * E_];
__device__ __nv_bfloat16 g_xl [(size_t)M_ * E_];
__device__ __nv_bfloat16 g_ath[(size_t)M_ * E_];
__device__ __nv_bfloat16 g_atl[(size_t)M_ * E_];
__device__ __nv_bfloat16 g_wvh[(size_t)E_ * E_];
__device__ __nv_bfloat16 g_wvl[(size_t)E_ * E_];
__device__ __nv_bfloat16 g_woh[(size_t)E_ * E_];
__device__ __nv_bfloat16 g_wol[(size_t)E_ * E_];

// ---------------------------------------------------------------------------
// hi/lo bf16 split
// ---------------------------------------------------------------------------
__device__ __forceinline__ void split_bf16(float a, __nv_bfloat16& hi, __nv_bfloat16& lo)
{
    hi = __float2bfloat16_rn(a);
    lo = __float2bfloat16_rn(__fadd_rn(a, -__bfloat162float(hi)));
}

__global__ __launch_bounds__(256)
void split_kernel(const float* __restrict__ src, __nv_bfloat16* __restrict__ hi,
                  __nv_bfloat16* __restrict__ lo, int n4)
{
    int i = blockIdx.x * 256 + threadIdx.x;
    if (i >= n4) return;
    float4 v = ((const float4*)src)[i];
    __nv_bfloat16 h0,h1,h2,h3,l0,l1,l2,l3;
    split_bf16(v.x,h0,l0); split_bf16(v.y,h1,l1);
    split_bf16(v.z,h2,l2); split_bf16(v.w,h3,l3);
    ((ushort4*)hi)[i] = make_ushort4(__bfloat16_as_ushort(h0), __bfloat16_as_ushort(h1),
                                     __bfloat16_as_ushort(h2), __bfloat16_as_ushort(h3));
    ((ushort4*)lo)[i] = make_ushort4(__bfloat16_as_ushort(l0), __bfloat16_as_ushort(l1),
                                     __bfloat16_as_ushort(l2), __bfloat16_as_ushort(l3));
}

// ---------------------------------------------------------------------------
// GEMM helpers (baseline ISA only: cp.async, ldmatrix, mma.sync)
// ---------------------------------------------------------------------------
__device__ __forceinline__ void cpasync16(void* dst, const void* src)
{
    unsigned d = (unsigned)__cvta_generic_to_shared(dst);
    asm volatile("cp.async.cg.shared.global [%0], [%1], 16;" :: "r"(d), "l"(src));
}

__device__ __forceinline__ void ldsm_x4(uint32_t* r, uint32_t saddr)
{
    asm volatile("ldmatrix.sync.aligned.m8n8.x4.shared.b16 {%0,%1,%2,%3}, [%4];"
        : "=r"(r[0]), "=r"(r[1]), "=r"(r[2]), "=r"(r[3]) : "r"(saddr));
}

__device__ __forceinline__ void mma_bf16(float* c, const uint32_t* a, const uint32_t* b)
{
    asm volatile(
        "mma.sync.aligned.m16n8k16.row.col.f32.bf16.bf16.f32 "
        "{%0,%1,%2,%3}, {%4,%5,%6,%7}, {%8,%9}, {%0,%1,%2,%3};\n"
        : "+f"(c[0]), "+f"(c[1]), "+f"(c[2]), "+f"(c[3])
        : "r"(a[0]), "r"(a[1]), "r"(a[2]), "r"(a[3]), "r"(b[0]), "r"(b[1]));
}

#define STAGE_BF16 (4 * 128 * TLD)          // Ah,Al,Wh,Wl tiles per stage
#define STAGE_BYTES (STAGE_BF16 * 2)
#define GSMEM_BYTES (2 * STAGE_BYTES)       // 81920

// ---------------------------------------------------------------------------
// Split-bf16 tensor-core GEMM: C[m,n] = rowmask(m)*(sum_k A[m,k]W[n,k]+bias[n])
// 128x128 block, 8 warps (2m x 4n), warp tile 64x32, BK=32, cp.async double
// buffer, ldmatrix.x4 fragment loads. 2 CTAs/SM.
// ---------------------------------------------------------------------------
__global__ __launch_bounds__(256, 2)
void gemm_split_kernel(const __nv_bfloat16* __restrict__ Ah,
                       const __nv_bfloat16* __restrict__ Al,
                       const __nv_bfloat16* __restrict__ Wh,
                       const __nv_bfloat16* __restrict__ Wl,
                       const float* __restrict__ bias,
                       const int* __restrict__ mask,
                       float* __restrict__ C)
{
    extern __shared__ __nv_bfloat16 sm[];
    const uint32_t sm32 = (uint32_t)__cvta_generic_to_shared(sm);

    const int tid  = threadIdx.x;
    const int lane = tid & 31;
    const int w    = tid >> 5;
    const int wm   = w >> 2;           // 0..1
    const int wn   = w & 3;            // 0..3
    const int row0 = blockIdx.y * 128;
    const int col0 = blockIdx.x * 128;
    const int lr   = lane >> 2;        // 0..7
    const int lq   = (lane & 3) << 1;  // 0,2,4,6

    // ldmatrix lane-address offsets (bytes) within each array:
    //   A x4: mat=lane>>3; rows (mat&1)*8 + (lane&7) of the 16-row tile,
    //         k-offset (mat>>1)*8.  -> regs {a0,a1,a2,a3} for m16k16.
    //   B x4: mat=lane>>3; covers n-tiles 2p,2p+1:
    //         n = (mat>>1)*8 + (lane&7), k-offset (mat&1)*8
    //         -> regs {b[2p][0], b[2p][1], b[2p+1][0], b[2p+1][1]}.
    const int amat = lane >> 3, arow = lane & 7;
    const uint32_t aoff = (uint32_t)(((wm * 64 + (amat & 1) * 8 + arow) * TLD
                                      + (amat >> 1) * 8) * 2);
    const uint32_t boff = (uint32_t)(((wn * 32 + (amat >> 1) * 8 + arow) * TLD
                                      + (amat & 1) * 8) * 2);

    float acc[4][4][4];
    #pragma unroll
    for (int ms = 0; ms < 4; ms++)
        #pragma unroll
        for (int ns = 0; ns < 4; ns++)
            #pragma unroll
            for (int t = 0; t < 4; t++) acc[ms][ns][t] = 0.0f;

    #define COPY_STAGE(stg, kbase) do {                                            \
        __nv_bfloat16* sb = sm + (stg) * STAGE_BF16;                               \
        _Pragma("unroll")                                                          \
        for (int half = 0; half < 2; half++) {                                     \
            int f  = tid + half * 256;                                             \
            int r  = f >> 2;                                                       \
            int cq = (f & 3) << 3;                                                 \
            size_t ga = (size_t)(row0 + r) * GK + (kbase) + cq;                    \
            size_t gw = (size_t)(col0 + r) * GK + (kbase) + cq;                    \
            cpasync16(sb + 0 * 128 * TLD + r * TLD + cq, Ah + ga);                 \
            cpasync16(sb + 1 * 128 * TLD + r * TLD + cq, Al + ga);                 \
            cpasync16(sb + 2 * 128 * TLD + r * TLD + cq, Wh + gw);                 \
            cpasync16(sb + 3 * 128 * TLD + r * TLD + cq, Wl + gw);                 \
        }                                                                          \
    } while (0)

    COPY_STAGE(0, 0);
    asm volatile("cp.async.commit_group;");

    const int NITER = GK / 32;     // 32
    for (int it = 0; it < NITER; it++) {
        if (it + 1 < NITER) COPY_STAGE((it + 1) & 1, (it + 1) * 32);
        asm volatile("cp.async.commit_group;");
        asm volatile("cp.async.wait_group 1;");
        __syncthreads();

        const uint32_t sb  = sm32 + (uint32_t)((it & 1) * STAGE_BYTES);
        const uint32_t sAh = sb;
        const uint32_t sAl = sb + 1 * 128 * TLD * 2;
        const uint32_t sWh = sb + 2 * 128 * TLD * 2;
        const uint32_t sWl = sb + 3 * 128 * TLD * 2;

        #pragma unroll
        for (int kk = 0; kk < 32; kk += 16) {
            const uint32_t kb = (uint32_t)(kk * 2);
            uint32_t bh[2][4], bl[2][4];
            #pragma unroll
            for (int p = 0; p < 2; p++) {
                uint32_t po = (uint32_t)(p * 16 * TLD * 2) + kb;
                ldsm_x4(bh[p], sWh + boff + po);
                ldsm_x4(bl[p], sWl + boff + po);
            }
            #pragma unroll
            for (int ms = 0; ms < 4; ms++) {
                uint32_t mo = (uint32_t)(ms * 16 * TLD * 2) + kb;
                uint32_t ah[4], al[4];
                ldsm_x4(ah, sAh + aoff + mo);
                ldsm_x4(al, sAl + aoff + mo);
                #pragma unroll
                for (int ns = 0; ns < 4; ns++) {
                    const uint32_t* bhp = &bh[ns >> 1][(ns & 1) * 2];
                    const uint32_t* blp = &bl[ns >> 1][(ns & 1) * 2];
                    mma_bf16(acc[ms][ns], ah, bhp);
                    mma_bf16(acc[ms][ns], ah, blp);
                    mma_bf16(acc[ms][ns], al, bhp);
                }
            }
        }
        __syncthreads();
    }

    // Epilogue: bias + optional row mask.
    #pragma unroll
    for (int ms = 0; ms < 4; ms++) {
        int r = row0 + wm * 64 + ms * 16 + lr;
        float m0 = mask ? (float)mask[r]     : 1.0f;
        float m1 = mask ? (float)mask[r + 8] : 1.0f;
        #pragma unroll
        for (int ns = 0; ns < 4; ns++) {
            int c = col0 + wn * 32 + ns * 8 + lq;
            float b0 = bias[c], b1 = bias[c + 1];
            float2 o0 = make_float2(m0 * (acc[ms][ns][0] + b0),
                                    m0 * (acc[ms][ns][1] + b1));
            float2 o1 = make_float2(m1 * (acc[ms][ns][2] + b0),
                                    m1 * (acc[ms][ns][3] + b1));
            *(float2*)(C + (size_t)r * E_ + c)       = o0;
            *(float2*)(C + (size_t)(r + 8) * E_ + c) = o1;
        }
    }
}

// ---------------------------------------------------------------------------
// K2: within-tile fwd-exclusive prefix + bwd-inclusive suffix along S.
// ---------------------------------------------------------------------------
__global__ __launch_bounds__(256)
void scan_local_kernel(const float* __restrict__ vm, float* __restrict__ pre,
                       float* __restrict__ suf, float* __restrict__ tsum)
{
    int e = blockIdx.x * 256 + threadIdx.x;
    int t = blockIdx.y;
    int b = blockIdx.z;
    size_t cbase = ((size_t)b * S_ + (size_t)t * TS) * E_ + e;
    const float* src = vm + cbase;
    float* pdst = pre + cbase;
    float* sdst = suf + cbase;

    float acc = 0.0f;
    #pragma unroll 8
    for (int s = 0; s < TS; s++) {
        float v = src[(size_t)s * E_];
        pdst[(size_t)s * E_] = acc;
        acc += v;
    }
    tsum[((size_t)b * NT + t) * E_ + e] = acc;

    acc = 0.0f;
    #pragma unroll 8
    for (int s = TS - 1; s >= 0; s--) {
        float v = src[(size_t)s * E_];
        acc += v;
        sdst[(size_t)s * E_] = acc;
    }
}

// ---------------------------------------------------------------------------
// K3: cross-tile fwd/bwd offsets.
// ---------------------------------------------------------------------------
__global__ __launch_bounds__(256)
void scan_tiles_kernel(const float* __restrict__ tsum,
                       float* __restrict__ toff_f, float* __restrict__ toff_b)
{
    int e = blockIdx.x * 256 + threadIdx.x;
    int b = blockIdx.y;
    float ts[NT];
    #pragma unroll
    for (int t = 0; t < NT; t++)
        ts[t] = tsum[((size_t)b * NT + t) * E_ + e];
    float acc = 0.0f;
    #pragma unroll
    for (int t = 0; t < NT; t++) {
        toff_f[((size_t)b * NT + t) * E_ + e] = acc;
        acc += ts[t];
    }
    acc = 0.0f;
    #pragma unroll
    for (int t = NT - 1; t >= 0; t--) {
        toff_b[((size_t)b * NT + t) * E_ + e] = acc;
        acc += ts[t];
    }
}

// ---------------------------------------------------------------------------
// K_w: per-(b,h,i) weights, Z in XLA:GPU row-reduce order (R7-validated —
// do not touch).
// ---------------------------------------------------------------------------
__device__ __forceinline__ float wval(int j, int i, int odd,
                                      float c0, float c1, float c2)
{
    if (j >= i) return c0;
    if (odd && j == i - 1) return c1;
    return c2;
}

__global__ __launch_bounds__(256)
void weights_kernel(const float* __restrict__ hier, float4* __restrict__ wts)
{
    int i = blockIdx.x * 256 + threadIdx.x;
    int h = blockIdx.y;
    int b = blockIdx.z;
    const float* hp = hier + ((size_t)b * H_ + h) * 3;
    float c0 = hp[0];
    float c1 = __fmul_rn(0.5f,  hp[1]);
    float c2 = __fmul_rn(0.25f, hp[2]);
    int odd = i & 1;

    float r[32];
    #pragma unroll 1
    for (int w = 0; w < 32; w++) {
        int jlo = w << 6;
        int jhi = jlo + 63;
        if (jlo >= i) {
            r[w] = __fmul_rn(64.0f, c0);
        } else if (jhi < i && !(odd && (i - 1) <= jhi)) {
            r[w] = __fmul_rn(64.0f, c2);
        } else {
            float p[32];
            #pragma unroll
            for (int t = 0; t < 32; t++) {
                int j = jlo + 2 * t;
                p[t] = __fadd_rn(wval(j, i, odd, c0, c1, c2),
                                 wval(j + 1, i, odd, c0, c1, c2));
            }
            #pragma unroll
            for (int s = 16; s > 0; s >>= 1)
                #pragma unroll
                for (int l = 0; l < 16; l++)
                    if (l < s) p[l] = __fadd_rn(p[l], p[l + s]);
            r[w] = p[0];
        }
    }
    #pragma unroll
    for (int s = 16; s > 0; s >>= 1)
        #pragma unroll
        for (int l = 0; l < 16; l++)
            if (l < s) r[l] = __fadd_rn(r[l], r[l + s]);

    float Z = __fadd_rn(r[0], 1e-8f);
    float4 o;
    o.x = __fdiv_rn(c0, Z);
    o.y = __fdiv_rn(c1, Z);
    o.z = __fdiv_rn(c2, Z);
    o.w = 0.0f;
    wts[((size_t)b * H_ + h) * S_ + i] = o;
}

// ---------------------------------------------------------------------------
// K4: combine; emits att directly as bf16 hi/lo split (K5 GEMM operand).
// ---------------------------------------------------------------------------
__global__ __launch_bounds__(256)
void combine_kernel(const float* __restrict__ pre, const float* __restrict__ suf,
                    const float* __restrict__ toff_f, const float* __restrict__ toff_b,
                    const float* __restrict__ vm, const float4* __restrict__ wts,
                    __nv_bfloat16* __restrict__ atth, __nv_bfloat16* __restrict__ attl)
{
    int i = blockIdx.x;
    int b = blockIdx.y;
    int odd = i & 1;
    int t = i >> 7;                                   // TS = 128

    #pragma unroll
    for (int c = 0; c < E_ / 256; c++) {
        int e = threadIdx.x + c * 256;
        int h = e >> 6;                               // dh = 64
        float4 w = wts[((size_t)b * H_ + h) * S_ + i];

        size_t base = ((size_t)b * S_ + i) * E_ + e;
        size_t tidx = ((size_t)b * NT + t) * E_ + e;
        float p  = pre[base] + toff_f[tidx];
        float sf = suf[base] + toff_b[tidx];
        float edge = odd ? vm[base - E_] : 0.0f;
        float val = w.x * sf + w.y * edge + w.z * (p - edge);
        __nv_bfloat16 hi, lo;
        split_bf16(val, hi, lo);
        atth[base] = hi;
        attl[base] = lo;
    }
}

// ---------------------------------------------------------------------------
// Launch. Inputs (metadata order):
// 0:x 1:attention_mask 2:level_indices(unused) 3:Wq 4:bq 5:Wk 6:bk
// 7:Wv 8:bv 9:hier 10:Wo 11:bo
// ---------------------------------------------------------------------------
extern "C" void kernel_launch(void* const* d_in, const int* in_sizes, int n_in,
                              void* d_out, int out_size)
{
    const float* x    = (const float*)d_in[0];
    const int*   am   = (const int*)  d_in[1];
    const float* Wv   = (const float*)d_in[7];
    const float* bv   = (const float*)d_in[8];
    const float* hier = (const float*)d_in[9];
    const float* Wo   = (const float*)d_in[10];
    const float* bo   = (const float*)d_in[11];
    float* out = (float*)d_out;

    float *vm, *pre, *suf, *tsum, *toff_f, *toff_b;
    float4* wts;
    __nv_bfloat16 *xh, *xl, *ath, *atl, *wvh, *wvl, *woh, *wol;
    cudaGetSymbolAddress((void**)&vm,     g_vm);
    cudaGetSymbolAddress((void**)&pre,    g_pre);
    cudaGetSymbolAddress((void**)&suf,    g_suf);
    cudaGetSymbolAddress((void**)&tsum,   g_tsum);
    cudaGetSymbolAddress((void**)&toff_f, g_tofff);
    cudaGetSymbolAddress((void**)&toff_b, g_toffb);
    cudaGetSymbolAddress((void**)&wts,    g_wts);
    cudaGetSymbolAddress((void**)&xh,     g_xh);
    cudaGetSymbolAddress((void**)&xl,     g_xl);
    cudaGetSymbolAddress((void**)&ath,    g_ath);
    cudaGetSymbolAddress((void**)&atl,    g_atl);
    cudaGetSymbolAddress((void**)&wvh,    g_wvh);
    cudaGetSymbolAddress((void**)&wvl,    g_wvl);
    cudaGetSymbolAddress((void**)&woh,    g_woh);
    cudaGetSymbolAddress((void**)&wol,    g_wol);

    static int smem_set = 0;
    if (!smem_set) {
        cudaFuncSetAttribute(gemm_split_kernel,
                             cudaFuncAttributeMaxDynamicSharedMemorySize,
                             GSMEM_BYTES);
        smem_set = 1;
    }

    // Split prep: x, Wv, Wo -> bf16 hi/lo
    split_kernel<<<(M_ * E_ / 4 + 255) / 256, 256>>>(x,  xh,  xl,  M_ * E_ / 4);
    split_kernel<<<(E_ * E_ / 4 + 255) / 256, 256>>>(Wv, wvh, wvl, E_ * E_ / 4);
    split_kernel<<<(E_ * E_ / 4 + 255) / 256, 256>>>(Wo, woh, wol, E_ * E_ / 4);

    dim3 gemm_grid(E_ / 128, M_ / 128);   // (8, 32)

    // K1: vm = mask * (x @ Wv^T + bv)
    gemm_split_kernel<<<gemm_grid, 256, GSMEM_BYTES>>>(xh, xl, wvh, wvl, bv, am, vm);

    // K_w: weights with XLA-tree Z
    weights_kernel<<<dim3(S_ / 256, H_, B_), 256>>>(hier, wts);

    // K2/K3: hierarchical fwd/bwd scans along S
    scan_local_kernel<<<dim3(E_ / 256, NT, B_), 256>>>(vm, pre, suf, tsum);
    scan_tiles_kernel<<<dim3(E_ / 256, B_), 256>>>(tsum, toff_f, toff_b);

    // K4: closed-form hierarchical attention -> att (bf16 hi/lo)
    combine_kernel<<<dim3(S_, B_), 256>>>(pre, suf, toff_f, toff_b, vm, wts, ath, atl);

    // K5: out = att @ Wo^T + bo
    gemm_split_kernel<<<gemm_grid, 256, GSMEM_BYTES>>>(ath, atl, woh, wol, bo,
                                                       nullptr, out);
}